// round 10
// baseline (speedup 1.0000x reference)
#include <cuda_runtime.h>
#include <cuda_bf16.h>
#include <cstdint>

#define B_    32
#define CIN_  32
#define COUT_ 64
#define H_    128
#define W_    128
#define HO_   126
#define WO_   126
#define MAXCN_ 64
#define TILES 14           // output rows per CTA strip; 9 strips x 14 = 126

__device__ float g_kdense[COUT_ * CIN_ * 9];

__global__ void fold_kernel(const float* __restrict__ w, const int* __restrict__ cn) {
    int idx = blockIdx.x * blockDim.x + threadIdx.x;
    if (idx >= COUT_ * CIN_ * 9) return;
    int k = idx % 9;
    int c = (idx / 9) % CIN_;
    int o = idx / (9 * CIN_);
    int n = cn[o];
    float v = 0.f;
    if (c < n)      v += w[(o * MAXCN_ + c) * 9 + k];
    if (c + 32 < n) v += w[(o * MAXCN_ + c + 32) * 9 + k];
    g_kdense[idx] = v;
}

// ---------------- smem layout (bytes) ----------------
// W:  [kw][hl][oc 64][k 96 pad->104] stride 208  -> 6 * 13312
// X:  ring[4][hl][px 130][c 32 pad->40] stride 80 -> 8 * 10400
// E:  transpose buffer [oc 64][wo pad 129 words]  -> 33024
#define WSTRIDE 208
#define WSIZE   13312
#define OFF_W   0
#define XSTRIDE 80
#define XSIZE   10400
#define OFF_X   79872       // 6*13312
#define OFF_E   163072      // OFF_X + 8*10400
#define SMEM_TOTAL 196096   // OFF_E + 64*129*4

__device__ __forceinline__ uint32_t smem_u32(const void* p) {
    uint32_t a;
    asm("{ .reg .u64 t; cvta.to.shared.u64 t, %1; cvt.u32.u64 %0, t; }" : "=r"(a) : "l"(p));
    return a;
}

__device__ __forceinline__ void ldsm4(uint32_t (&r)[4], uint32_t addr) {
    asm volatile("ldmatrix.sync.aligned.m8n8.x4.shared.b16 {%0,%1,%2,%3}, [%4];"
                 : "=r"(r[0]), "=r"(r[1]), "=r"(r[2]), "=r"(r[3]) : "r"(addr));
}

__device__ __forceinline__ void mma16816(float (&d)[4], const uint32_t (&a)[4],
                                         uint32_t b0, uint32_t b1) {
    asm volatile("mma.sync.aligned.m16n8k16.row.col.f32.bf16.bf16.f32 "
                 "{%0,%1,%2,%3}, {%4,%5,%6,%7}, {%8,%9}, {%0,%1,%2,%3};"
                 : "+f"(d[0]), "+f"(d[1]), "+f"(d[2]), "+f"(d[3])
                 : "r"(a[0]), "r"(a[1]), "r"(a[2]), "r"(a[3]), "r"(b0), "r"(b1));
}

__device__ __forceinline__ void cvt_split(float v, __nv_bfloat16& hi, __nv_bfloat16& lo) {
    hi = __float2bfloat16(v);
    lo = __float2bfloat16(v - __bfloat162float(hi));
}

// stage input row ir (32 c x 128 px, hi/lo) into ring slot ir&3, layout [px][c]
__device__ __forceinline__ void stage(char* smem, const float* xb, int ir, int tid) {
    char* hbase = smem + OFF_X + (size_t)((ir & 3) * 2) * XSIZE;
    for (int i = tid; i < CIN_ * W_; i += 256) {
        int c = i >> 7, px = i & 127;                 // lanes = consecutive px -> coalesced LDG
        float v = __ldg(xb + ((long)c * H_ + ir) * W_ + px);
        __nv_bfloat16 hi, lo;
        cvt_split(v, hi, lo);
        *(__nv_bfloat16*)(hbase + px * XSTRIDE + c * 2) = hi;
        *(__nv_bfloat16*)(hbase + XSIZE + px * XSTRIDE + c * 2) = lo;
    }
}

__global__ __launch_bounds__(256, 1)
void conv_kernel(const float* __restrict__ x,
                 const float* __restrict__ bias,
                 float* __restrict__ out) {
    extern __shared__ __align__(128) char smem[];
    const uint32_t sb  = smem_u32(smem);
    const int tid  = threadIdx.x;
    const int lane = tid & 31;
    const int w    = tid >> 5;
    const int b    = blockIdx.x;
    const int r0   = blockIdx.y * TILES;
    const float* xb = x + (long)b * CIN_ * H_ * W_;

    // zero the pad rows 128,129 of every X buffer (read by kw-shift for discarded wo>=126)
    for (int i = tid; i < 8 * 2 * 40; i += 256) {
        int buf = i / 80, rr = (i / 40) & 1, col = i % 40;
        *(uint16_t*)(smem + OFF_X + (size_t)buf * XSIZE + (128 + rr) * XSTRIDE + col * 2) = 0;
    }
    // stage weights: W[kw][hl][oc][k = kh*32 + c]
    for (int i = tid; i < 3 * COUT_ * 96; i += 256) {
        int k = i % 96, oc = (i / 96) & 63, kw = i / (96 * 64);
        int c = k & 31, kh = k >> 5;
        float v = g_kdense[(oc * CIN_ + c) * 9 + kh * 3 + kw];
        __nv_bfloat16 hi, lo;
        cvt_split(v, hi, lo);
        char* base = smem + OFF_W + (size_t)(kw * 2) * WSIZE + oc * WSTRIDE + k * 2;
        *(__nv_bfloat16*)base = hi;
        *(__nv_bfloat16*)(base + WSIZE) = lo;
    }
    stage(smem, xb, r0, tid);
    stage(smem, xb, r0 + 1, tid);

    const int px0 = w * 16;
    // per-lane invariant ldmatrix offsets
    const uint32_t a_lane = (uint32_t)(((lane & 7) + ((lane >> 3) & 1) * 8) * XSTRIDE
                                       + ((lane >> 4) & 1) * 16);
    const uint32_t b_lane = (uint32_t)(((lane & 7) + ((lane >> 4) & 1) * 8) * WSTRIDE
                                       + ((lane >> 3) & 1) * 16);

    for (int pl = 0; pl < TILES / 2; ++pl) {
        const int rg = r0 + 2 * pl;
        stage(smem, xb, rg + 2, tid);
        stage(smem, xb, rg + 3, tid);
        __syncthreads();

        float acc[2][8][4];
        #pragma unroll
        for (int rr = 0; rr < 2; ++rr)
            #pragma unroll
            for (int nt = 0; nt < 8; ++nt)
                #pragma unroll
                for (int j = 0; j < 4; ++j) acc[rr][nt][j] = 0.f;

        #pragma unroll
        for (int s = 0; s < 6; ++s) {
            const int kh = s >> 1;
            const uint32_t acoff = (s & 1) * 32;
            const uint32_t bcoff = (s >> 1) * 64 + (s & 1) * 32;
            #pragma unroll
            for (int kw = 0; kw < 3; ++kw) {
                // B (weight) fragments: 8 n-tiles, hi & lo
                uint32_t bh[16], bl[16];
                const uint32_t wbH = sb + OFF_W + (uint32_t)(kw * 2) * WSIZE + bcoff + b_lane;
                #pragma unroll
                for (int t = 0; t < 4; ++t) {
                    uint32_t r4[4];
                    ldsm4(r4, wbH + (uint32_t)(t * 16) * WSTRIDE);
                    bh[4 * t + 0] = r4[0]; bh[4 * t + 1] = r4[1];
                    bh[4 * t + 2] = r4[2]; bh[4 * t + 3] = r4[3];
                }
                #pragma unroll
                for (int t = 0; t < 4; ++t) {
                    uint32_t r4[4];
                    ldsm4(r4, wbH + WSIZE + (uint32_t)(t * 16) * WSTRIDE);
                    bl[4 * t + 0] = r4[0]; bl[4 * t + 1] = r4[1];
                    bl[4 * t + 2] = r4[2]; bl[4 * t + 3] = r4[3];
                }
                #pragma unroll
                for (int rr = 0; rr < 2; ++rr) {
                    const int slot = (rg + rr + kh) & 3;
                    const uint32_t xbase = sb + OFF_X + (uint32_t)(slot * 2) * XSIZE;
                    const uint32_t aaddr = xbase + (uint32_t)(px0 + kw) * XSTRIDE + acoff + a_lane;
                    uint32_t ah[4], al[4];
                    ldsm4(ah, aaddr);
                    ldsm4(al, aaddr + XSIZE);
                    #pragma unroll
                    for (int nt = 0; nt < 8; ++nt) {
                        mma16816(acc[rr][nt], ah, bh[2 * nt], bh[2 * nt + 1]);  // Xh*Wh
                        mma16816(acc[rr][nt], al, bh[2 * nt], bh[2 * nt + 1]);  // Xl*Wh
                        mma16816(acc[rr][nt], ah, bl[2 * nt], bl[2 * nt + 1]);  // Xh*Wl
                    }
                }
            }
        }

        // epilogue: per row, transpose through smem, coalesced bias+store
        #pragma unroll
        for (int rr = 0; rr < 2; ++rr) {
            const int ho = rg + rr;
            #pragma unroll
            for (int nt = 0; nt < 8; ++nt)
                #pragma unroll
                for (int j = 0; j < 4; ++j) {
                    const int oc = nt * 8 + (lane & 3) * 2 + (j & 1);
                    const int wo = px0 + (lane >> 2) + (j >> 1) * 8;
                    *(float*)(smem + OFF_E + (size_t)(oc * 129 + wo) * 4) = acc[rr][nt][j];
                }
            __syncthreads();
            for (int i = 0; i < 32; ++i) {
                const int lin = i * 256 + tid;
                const int oc = lin >> 7, wo = lin & 127;
                if (wo < WO_) {
                    float v = *(float*)(smem + OFF_E + (size_t)(oc * 129 + wo) * 4)
                            + __ldg(bias + ((long)oc * HO_ + ho) * WO_ + wo);
                    out[(((long)b * COUT_ + oc) * HO_ + ho) * WO_ + wo] = v;
                }
            }
            __syncthreads();
        }
    }
}

extern "C" void kernel_launch(void* const* d_in, const int* in_sizes, int n_in,
                              void* d_out, int out_size) {
    const float* x    = (const float*)d_in[0];   // [32,32,128,128]
    const float* w    = (const float*)d_in[1];   // [64,64,3,3]
    const float* bias = (const float*)d_in[2];   // [64,126,126]
    const int*   cn   = (const int*)d_in[3];     // [64]
    float* out = (float*)d_out;                  // [32,64,126,126]

    fold_kernel<<<(COUT_ * CIN_ * 9 + 255) / 256, 256>>>(w, cn);
    cudaFuncSetAttribute(conv_kernel, cudaFuncAttributeMaxDynamicSharedMemorySize, SMEM_TOTAL);
    conv_kernel<<<dim3(B_, 9), 256, SMEM_TOTAL>>>(x, bias, out);
}

// round 11
// speedup vs baseline: 2.7924x; 2.7924x over previous
#include <cuda_runtime.h>
#include <cuda_bf16.h>
#include <cstdint>

#define B_    32
#define CIN_  32
#define COUT_ 64
#define H_    128
#define W_    128
#define HO_   126
#define WO_   126
#define MAXCN_ 64
#define TILES 14           // output rows per CTA strip; 9 strips x 14 = 126

// ---------------- prepared global buffers ----------------
// X converted: [b][row][hl][px 128][c 32] bf16, as uint4 chunks (512 per (b,row,hl))
__device__ uint4 g_xcvt[(size_t)B_ * H_ * 2 * 512];      // 64 MB
// W folded+split: [kw][hl][oc 64][k 96 pad->104] bf16 -> 79872 B = 4992 uint4
__device__ uint4 g_wfold[4992];

// ---------------- smem layout (bytes) ----------------
#define WSTRIDE 208
#define WSIZE   13312
#define OFF_W   0
#define XSTRIDE 80
#define XSIZE   10400        // 130 px-rows * 80
#define OFF_X   79872        // 6*13312
#define OFF_E   163072       // OFF_X + 8*10400  (ring 4 slots x 2 hl)
#define SMEM_TOTAL 196096    // OFF_E + 64*129*4

__device__ __forceinline__ void cvt_split(float v, __nv_bfloat16& hi, __nv_bfloat16& lo) {
    hi = __float2bfloat16(v);
    lo = __float2bfloat16(v - __bfloat162float(hi));
}

// fold connect-mask + duplicate channels, split hi/lo, write final layout
__global__ void cvt_w_kernel(const float* __restrict__ w, const int* __restrict__ cn) {
    int idx = blockIdx.x * blockDim.x + threadIdx.x;     // o(64) x kh(3) x kw(3) x c(32)
    if (idx >= COUT_ * 9 * CIN_) return;
    int c  = idx & 31;
    int kw = (idx >> 5) % 3;
    int kh = ((idx >> 5) / 3) % 3;
    int o  = idx / (32 * 9);
    int n  = cn[o];
    float v = 0.f;
    if (c < n)      v += w[(o * MAXCN_ + c) * 9 + kh * 3 + kw];
    if (c + 32 < n) v += w[(o * MAXCN_ + c + 32) * 9 + kh * 3 + kw];
    __nv_bfloat16 hi, lo;
    cvt_split(v, hi, lo);
    int k = kh * 32 + c;
    char* base = (char*)g_wfold;
    *(__nv_bfloat16*)(base + ((size_t)(kw * 2 + 0) * 64 + o) * WSTRIDE + k * 2) = hi;
    *(__nv_bfloat16*)(base + ((size_t)(kw * 2 + 1) * 64 + o) * WSTRIDE + k * 2) = lo;
}

// convert x to bf16 hi/lo in stage-ready layout: [b][row][hl][px][c]
__global__ void cvt_x_kernel(const float* __restrict__ x) {
    __shared__ float s[CIN_][129];
    const int row = blockIdx.x, b = blockIdx.y, tid = threadIdx.x;
    for (int i = tid; i < CIN_ * W_; i += 256) {
        int c = i >> 7, px = i & 127;
        s[c][px] = x[(((size_t)b * CIN_ + c) * H_ + row) * W_ + px];    // coalesced over px
    }
    __syncthreads();
    for (int q2 = tid; q2 < 1024; q2 += 256) {
        int hl = q2 >> 9, q = q2 & 511;
        int px = q >> 2, c0 = (q & 3) * 8;
        __nv_bfloat16 v[8];
        #pragma unroll
        for (int j = 0; j < 8; ++j) {
            float f = s[c0 + j][px];
            __nv_bfloat16 hi, lo;
            cvt_split(f, hi, lo);
            v[j] = hl ? lo : hi;
        }
        g_xcvt[(((size_t)b * H_ + row) * 2 + hl) * 512 + q] = *(const uint4*)v;
    }
}

__device__ __forceinline__ uint32_t smem_u32(const void* p) {
    uint32_t a;
    asm("{ .reg .u64 t; cvta.to.shared.u64 t, %1; cvt.u32.u64 %0, t; }" : "=r"(a) : "l"(p));
    return a;
}
__device__ __forceinline__ void ldsm4(uint32_t* r, uint32_t addr) {
    asm volatile("ldmatrix.sync.aligned.m8n8.x4.shared.b16 {%0,%1,%2,%3}, [%4];"
                 : "=r"(r[0]), "=r"(r[1]), "=r"(r[2]), "=r"(r[3]) : "r"(addr));
}
__device__ __forceinline__ void mma16816(float (&d)[4], const uint32_t* a,
                                         uint32_t b0, uint32_t b1) {
    asm volatile("mma.sync.aligned.m16n8k16.row.col.f32.bf16.bf16.f32 "
                 "{%0,%1,%2,%3}, {%4,%5,%6,%7}, {%8,%9}, {%0,%1,%2,%3};"
                 : "+f"(d[0]), "+f"(d[1]), "+f"(d[2]), "+f"(d[3])
                 : "r"(a[0]), "r"(a[1]), "r"(a[2]), "r"(a[3]), "r"(b0), "r"(b1));
}

__global__ __launch_bounds__(512, 1)
void conv_kernel(const float* __restrict__ bias, float* __restrict__ out) {
    extern __shared__ __align__(128) char smem[];
    const uint32_t sb = smem_u32(smem);
    const int tid  = threadIdx.x;
    const int lane = tid & 31;
    const int w    = tid >> 5;          // 16 warps
    const int g    = w & 7;             // px group (16 px)
    const int oh   = w >> 3;            // oc half  (32 oc)
    const int px0  = g * 16;
    const int b    = blockIdx.x;
    const int r0   = blockIdx.y * TILES;

    // zero X pad px-rows 128,129 of all 8 buffers
    for (int i = tid; i < 80; i += 512) {
        int buf = i / 10, q = i % 10;
        uint4 z = {0, 0, 0, 0};
        *(uint4*)(smem + OFF_X + (size_t)buf * XSIZE + 128 * XSTRIDE + q * 16) = z;
    }
    // copy W (linear, layout-identical)
    for (int i = tid; i < 4992; i += 512)
        ((uint4*)smem)[i] = g_wfold[i];

    // prologue: stage rows r0..r0+3 into ring
    const uint4* xg = g_xcvt + (size_t)b * H_ * 2 * 512;
    #pragma unroll
    for (int k = 0; k < 8; ++k) {
        int ci = tid + k * 512;
        int rowi = ci >> 10, rem = ci & 1023, hl = rem >> 9, q = rem & 511;
        uint4 v = xg[((size_t)(r0 + rowi) * 2 + hl) * 512 + q];
        *(uint4*)(smem + OFF_X + (size_t)(((r0 + rowi) & 3) * 2 + hl) * XSIZE
                  + (q >> 2) * XSTRIDE + (q & 3) * 16) = v;
    }
    __syncthreads();

    const uint32_t a_lane = (uint32_t)(((lane & 7) + ((lane >> 3) & 1) * 8) * XSTRIDE
                                       + ((lane >> 4) & 1) * 16);
    const uint32_t b_lane = (uint32_t)(((lane & 7) + ((lane >> 4) & 1) * 8) * WSTRIDE
                                       + ((lane >> 3) & 1) * 16);

    for (int pl = 0; pl < TILES / 2; ++pl) {
        const int rg = r0 + 2 * pl;

        // register prefetch of next row pair (hidden behind compute)
        uint4 pf[4];
        if (pl < 6) {
            #pragma unroll
            for (int k = 0; k < 4; ++k) {
                int ci = tid + k * 512;
                int rowi = ci >> 10, hl = (ci >> 9) & 1, q = ci & 511;
                pf[k] = xg[((size_t)(rg + 4 + rowi) * 2 + hl) * 512 + q];
            }
        }

        float acc[2][4][4];
        #pragma unroll
        for (int rr = 0; rr < 2; ++rr)
            #pragma unroll
            for (int t = 0; t < 4; ++t)
                #pragma unroll
                for (int j = 0; j < 4; ++j) acc[rr][t][j] = 0.f;

        #pragma unroll
        for (int s = 0; s < 6; ++s) {
            const int kh = s >> 1;
            const uint32_t acoff = (s & 1) * 32;
            const uint32_t bcoff = (uint32_t)(kh * 64 + (s & 1) * 32);
            #pragma unroll
            for (int kw = 0; kw < 3; ++kw) {
                uint32_t bh[8], bl[8];
                const uint32_t wbH = sb + OFF_W + (uint32_t)(kw * 2) * WSIZE
                                   + (uint32_t)(oh * 32) * WSTRIDE + bcoff + b_lane;
                #pragma unroll
                for (int t2 = 0; t2 < 2; ++t2) {
                    ldsm4(&bh[4 * t2], wbH + (uint32_t)(t2 * 16) * WSTRIDE);
                    ldsm4(&bl[4 * t2], wbH + WSIZE + (uint32_t)(t2 * 16) * WSTRIDE);
                }
                #pragma unroll
                for (int rr = 0; rr < 2; ++rr) {
                    const int slot = (rg + rr + kh) & 3;
                    const uint32_t aaddr = sb + OFF_X + (uint32_t)(slot * 2) * XSIZE
                                         + (uint32_t)(px0 + kw) * XSTRIDE + acoff + a_lane;
                    uint32_t ah[4], al[4];
                    ldsm4(ah, aaddr);
                    ldsm4(al, aaddr + XSIZE);
                    #pragma unroll
                    for (int t = 0; t < 4; ++t) {
                        mma16816(acc[rr][t], ah, bh[2 * t], bh[2 * t + 1]);  // Xh*Wh
                        mma16816(acc[rr][t], al, bh[2 * t], bh[2 * t + 1]);  // Xl*Wh
                        mma16816(acc[rr][t], ah, bl[2 * t], bl[2 * t + 1]);  // Xh*Wl
                    }
                }
            }
        }

        // epilogue: per row, transpose via E, coalesced bias+store
        #pragma unroll
        for (int rr = 0; rr < 2; ++rr) {
            const int ho = rg + rr;
            __syncthreads();   // prev E readers done
            #pragma unroll
            for (int t = 0; t < 4; ++t)
                #pragma unroll
                for (int j = 0; j < 4; ++j) {
                    const int oc = oh * 32 + t * 8 + (lane & 3) * 2 + (j & 1);
                    const int wo = px0 + (lane >> 2) + (j >> 1) * 8;
                    *(float*)(smem + OFF_E + (size_t)(oc * 129 + wo) * 4) = acc[rr][t][j];
                }
            __syncthreads();
            #pragma unroll
            for (int i = 0; i < 16; ++i) {
                const int lin = i * 512 + tid;
                const int oc = lin >> 7, wo = lin & 127;
                if (wo < WO_) {
                    float v = *(float*)(smem + OFF_E + (size_t)(oc * 129 + wo) * 4)
                            + __ldg(bias + ((size_t)oc * HO_ + ho) * WO_ + wo);
                    out[(((size_t)b * COUT_ + oc) * HO_ + ho) * WO_ + wo] = v;
                }
            }
        }

        // store prefetched rows into ring (slots of consumed rows rg, rg+1)
        if (pl < 6) {
            __syncthreads();   // all compute/store reads done
            #pragma unroll
            for (int k = 0; k < 4; ++k) {
                int ci = tid + k * 512;
                int rowi = ci >> 10, hl = (ci >> 9) & 1, q = ci & 511;
                *(uint4*)(smem + OFF_X + (size_t)(((rg + 4 + rowi) & 3) * 2 + hl) * XSIZE
                          + (q >> 2) * XSTRIDE + (q & 3) * 16) = pf[k];
            }
            __syncthreads();   // visible to next compute
        }
    }
}

extern "C" void kernel_launch(void* const* d_in, const int* in_sizes, int n_in,
                              void* d_out, int out_size) {
    const float* x    = (const float*)d_in[0];   // [32,32,128,128]
    const float* w    = (const float*)d_in[1];   // [64,64,3,3]
    const float* bias = (const float*)d_in[2];   // [64,126,126]
    const int*   cn   = (const int*)d_in[3];     // [64]
    float* out = (float*)d_out;                  // [32,64,126,126]

    cvt_w_kernel<<<(COUT_ * 9 * CIN_ + 255) / 256, 256>>>(w, cn);
    cvt_x_kernel<<<dim3(H_, B_), 256>>>(x);
    cudaFuncSetAttribute(conv_kernel, cudaFuncAttributeMaxDynamicSharedMemorySize, SMEM_TOTAL);
    conv_kernel<<<dim3(B_, 9), 512, SMEM_TOTAL>>>(bias, out);
}

// round 12
// speedup vs baseline: 3.1650x; 1.1334x over previous
#include <cuda_runtime.h>
#include <cuda_fp16.h>
#include <cstdint>

#define B_    32
#define CIN_  32
#define COUT_ 64
#define H_    128
#define W_    128
#define HO_   126
#define WO_   126
#define MAXCN_ 64
#define TILES 14           // output rows per CTA strip; 9 strips x 14 = 126

// ---------------- prepared global buffers ----------------
// X converted to fp16: [b][row][px 128][c 32], 512 uint4 per (b,row)  -> 32 MB
__device__ uint4 g_xcvt[(size_t)B_ * H_ * 512];
// W folded + fp16 hi/lo split: [kw][hl][oc 64][k 96 pad->104] -> 79872 B
__device__ uint4 g_wfold[4992];

// ---------------- smem layout (bytes) ----------------
#define WSTRIDE 208
#define WSIZE   13312
#define OFF_W   0
#define XSTRIDE 80           // 32c fp16 = 64B + 16B pad; conflict-free ldsm phases
#define XSIZE   10400        // 130 px-rows * 80
#define OFF_X   79872
#define OFF_E   121472       // E: [oc 64][wo pad 132] f32 = 33792 B
#define SMEM_TOTAL 155264

__global__ void cvt_w_kernel(const float* __restrict__ w, const int* __restrict__ cn) {
    int idx = blockIdx.x * blockDim.x + threadIdx.x;     // o(64) x kh(3) x kw(3) x c(32)
    if (idx >= COUT_ * 9 * CIN_) return;
    int c  = idx & 31;
    int kw = (idx >> 5) % 3;
    int kh = ((idx >> 5) / 3) % 3;
    int o  = idx / (32 * 9);
    int n  = cn[o];
    float v = 0.f;
    if (c < n)      v += w[(o * MAXCN_ + c) * 9 + kh * 3 + kw];
    if (c + 32 < n) v += w[(o * MAXCN_ + c + 32) * 9 + kh * 3 + kw];
    __half hh = __float2half_rn(v);
    __half hl = __float2half_rn(v - __half2float(hh));
    int k = kh * 32 + c;
    char* base = (char*)g_wfold;
    *(__half*)(base + ((size_t)(kw * 2 + 0) * 64 + o) * WSTRIDE + k * 2) = hh;
    *(__half*)(base + ((size_t)(kw * 2 + 1) * 64 + o) * WSTRIDE + k * 2) = hl;
}

// x -> fp16 in stage-ready layout [b][row][px][c]
__global__ void cvt_x_kernel(const float* __restrict__ x) {
    __shared__ float s[CIN_][129];
    const int row = blockIdx.x, b = blockIdx.y, tid = threadIdx.x;
    for (int i = tid; i < CIN_ * W_; i += 256) {
        int c = i >> 7, px = i & 127;
        s[c][px] = x[(((size_t)b * CIN_ + c) * H_ + row) * W_ + px];   // coalesced over px
    }
    __syncthreads();
    for (int q = tid; q < 512; q += 256) {
        int px = q >> 2, c0 = (q & 3) * 8;
        __align__(16) __half v[8];
        #pragma unroll
        for (int j = 0; j < 8; ++j) v[j] = __float2half_rn(s[c0 + j][px]);
        g_xcvt[((size_t)b * H_ + row) * 512 + q] = *(const uint4*)v;
    }
}

__device__ __forceinline__ uint32_t smem_u32(const void* p) {
    uint32_t a;
    asm("{ .reg .u64 t; cvta.to.shared.u64 t, %1; cvt.u32.u64 %0, t; }" : "=r"(a) : "l"(p));
    return a;
}
__device__ __forceinline__ void ldsm4(uint32_t* r, uint32_t addr) {
    asm volatile("ldmatrix.sync.aligned.m8n8.x4.shared.b16 {%0,%1,%2,%3}, [%4];"
                 : "=r"(r[0]), "=r"(r[1]), "=r"(r[2]), "=r"(r[3]) : "r"(addr));
}
__device__ __forceinline__ void mma16816(float (&d)[4], const uint32_t* a,
                                         uint32_t b0, uint32_t b1) {
    asm volatile("mma.sync.aligned.m16n8k16.row.col.f32.f16.f16.f32 "
                 "{%0,%1,%2,%3}, {%4,%5,%6,%7}, {%8,%9}, {%0,%1,%2,%3};"
                 : "+f"(d[0]), "+f"(d[1]), "+f"(d[2]), "+f"(d[3])
                 : "r"(a[0]), "r"(a[1]), "r"(a[2]), "r"(a[3]), "r"(b0), "r"(b1));
}

__global__ __launch_bounds__(512, 1)
void conv_kernel(const float* __restrict__ bias, float* __restrict__ out) {
    extern __shared__ __align__(128) char smem[];
    const uint32_t sb = smem_u32(smem);
    const int tid  = threadIdx.x;
    const int lane = tid & 31;
    const int w    = tid >> 5;          // 16 warps
    const int g    = w & 7;             // px group (16 px)
    const int oh   = w >> 3;            // oc half  (32 oc)
    const int px0  = g * 16;
    const int b    = blockIdx.x;
    const int r0   = blockIdx.y * TILES;

    // zero X pad px-rows 128,129 of all 4 ring slots
    for (int i = tid; i < 40; i += 512) {
        int slot = i / 10, rem = i % 10, rr = rem / 5, q = rem % 5;
        uint4 z = {0, 0, 0, 0};
        *(uint4*)(smem + OFF_X + (size_t)slot * XSIZE + (128 + rr) * XSTRIDE + q * 16) = z;
    }
    // copy W (layout-identical)
    for (int i = tid; i < 4992; i += 512)
        ((uint4*)smem)[i] = g_wfold[i];

    // prologue: stage rows r0..r0+3 (1 uint4 per thread per row)
    const uint4* xg = g_xcvt + (size_t)b * H_ * 512;
    #pragma unroll
    for (int j = 0; j < 4; ++j) {
        uint4 v = xg[(size_t)(r0 + j) * 512 + tid];
        *(uint4*)(smem + OFF_X + (size_t)((r0 + j) & 3) * XSIZE
                  + (tid >> 2) * XSTRIDE + (tid & 3) * 16) = v;
    }
    __syncthreads();

    const uint32_t a_lane = (uint32_t)(((lane & 7) + ((lane >> 3) & 1) * 8) * XSTRIDE
                                       + ((lane >> 4) & 1) * 16);
    const uint32_t b_lane = (uint32_t)(((lane & 7) + ((lane >> 4) & 1) * 8) * WSTRIDE
                                       + ((lane >> 3) & 1) * 16);

    for (int pl = 0; pl < TILES / 2; ++pl) {
        const int rg = r0 + 2 * pl;

        // register prefetch next row pair (hidden behind compute)
        uint4 pf0, pf1;
        if (pl < 6) {
            pf0 = xg[(size_t)(rg + 4) * 512 + tid];
            pf1 = xg[(size_t)(rg + 5) * 512 + tid];
        }

        float acc[2][4][4];
        #pragma unroll
        for (int rr = 0; rr < 2; ++rr)
            #pragma unroll
            for (int t = 0; t < 4; ++t)
                #pragma unroll
                for (int j = 0; j < 4; ++j) acc[rr][t][j] = 0.f;

        #pragma unroll
        for (int s = 0; s < 6; ++s) {
            const int kh = s >> 1;
            const uint32_t acoff = (s & 1) * 32;
            const uint32_t bcoff = (uint32_t)(kh * 64 + (s & 1) * 32);
            #pragma unroll
            for (int kw = 0; kw < 3; ++kw) {
                uint32_t bh[8], bl[8];
                const uint32_t wb = sb + OFF_W + (uint32_t)(kw * 2) * WSIZE
                                  + (uint32_t)(oh * 32) * WSTRIDE + bcoff + b_lane;
                ldsm4(bh,     wb);
                ldsm4(bh + 4, wb + 16u * WSTRIDE);
                ldsm4(bl,     wb + WSIZE);
                ldsm4(bl + 4, wb + WSIZE + 16u * WSTRIDE);
                #pragma unroll
                for (int rr = 0; rr < 2; ++rr) {
                    const int slot = (rg + rr + kh) & 3;
                    const uint32_t aaddr = sb + OFF_X + (uint32_t)slot * XSIZE
                                         + (uint32_t)(px0 + kw) * XSTRIDE + acoff + a_lane;
                    uint32_t ah[4];
                    ldsm4(ah, aaddr);
                    #pragma unroll
                    for (int t = 0; t < 4; ++t) {
                        mma16816(acc[rr][t], ah, bh[2 * t], bh[2 * t + 1]);  // X*Wh
                        mma16816(acc[rr][t], ah, bl[2 * t], bl[2 * t + 1]);  // X*Wl
                    }
                }
            }
        }

        __syncthreads();                     // X reads + prev E readers done
        if (pl < 6) {
            *(uint4*)(smem + OFF_X + (size_t)((rg + 4) & 3) * XSIZE
                      + (tid >> 2) * XSTRIDE + (tid & 3) * 16) = pf0;
            *(uint4*)(smem + OFF_X + (size_t)((rg + 5) & 3) * XSIZE
                      + (tid >> 2) * XSTRIDE + (tid & 3) * 16) = pf1;
        }

        #pragma unroll
        for (int rr = 0; rr < 2; ++rr) {
            const int ho = rg + rr;
            if (rr == 1) __syncthreads();    // row-0 E readers done
            #pragma unroll
            for (int t = 0; t < 4; ++t)
                #pragma unroll
                for (int j = 0; j < 4; ++j) {
                    const int oc = oh * 32 + t * 8 + (lane & 3) * 2 + (j & 1);
                    const int wo = px0 + (lane >> 2) + (j >> 1) * 8;
                    *(float*)(smem + OFF_E + (size_t)(oc * 132 + wo) * 4) = acc[rr][t][j];
                }
            __syncthreads();
            #pragma unroll
            for (int i = 0; i < 4; ++i) {
                const int idx = i * 512 + tid;
                const int oc = idx >> 5, wo4 = (idx & 31) * 4;
                uint4 e = *(const uint4*)(smem + OFF_E + (size_t)(oc * 132 + wo4) * 4);
                const float ev[4] = {__uint_as_float(e.x), __uint_as_float(e.y),
                                     __uint_as_float(e.z), __uint_as_float(e.w)};
                #pragma unroll
                for (int m = 0; m < 4; ++m) {
                    const int wo = wo4 + m;
                    if (wo < WO_) {
                        float v = ev[m] + __ldg(bias + ((size_t)oc * HO_ + ho) * WO_ + wo);
                        out[(((size_t)b * COUT_ + oc) * HO_ + ho) * WO_ + wo] = v;
                    }
                }
            }
        }
    }
}

extern "C" void kernel_launch(void* const* d_in, const int* in_sizes, int n_in,
                              void* d_out, int out_size) {
    const float* x    = (const float*)d_in[0];   // [32,32,128,128]
    const float* w    = (const float*)d_in[1];   // [64,64,3,3]
    const float* bias = (const float*)d_in[2];   // [64,126,126]
    const int*   cn   = (const int*)d_in[3];     // [64]
    float* out = (float*)d_out;                  // [32,64,126,126]

    cvt_w_kernel<<<(COUT_ * 9 * CIN_ + 255) / 256, 256>>>(w, cn);
    cvt_x_kernel<<<dim3(H_, B_), 256>>>(x);
    cudaFuncSetAttribute(conv_kernel, cudaFuncAttributeMaxDynamicSharedMemorySize, SMEM_TOTAL);
    conv_kernel<<<dim3(B_, 9), 512, SMEM_TOTAL>>>(bias, out);
}

// round 13
// speedup vs baseline: 3.9735x; 1.2554x over previous
#include <cuda_runtime.h>
#include <cuda_fp16.h>
#include <cstdint>

#define B_    32
#define CIN_  32
#define COUT_ 64
#define H_    128
#define W_    128
#define HO_   126
#define WO_   126
#define MAXCN_ 64
#define TILES 14           // output rows per CTA strip; 9 strips x 14 = 126

// ---------------- prepared global buffers ----------------
// X converted to fp16: [b][row][px 128][c 32], 512 uint4 per (b,row)  -> 32 MB
__device__ uint4 g_xcvt[(size_t)B_ * H_ * 512];
// W folded to fp16: [kw][oc 64][k 96 pad->104] -> 39936 B
__device__ uint4 g_wfold[2496];

// ---------------- smem layout (bytes) ----------------
#define WSTRIDE 208
#define WSIZE   13312
#define OFF_W   0
#define XSTRIDE 80           // 32c fp16 = 64B + 16B pad; conflict-free ldsm phases
#define XSIZE   10400        // 130 px-rows * 80
#define OFF_X   39936        // 3 * WSIZE
#define OFF_E   81536        // OFF_X + 4*XSIZE ; E: [oc 64][wo pad 132] f32 = 33792 B
#define SMEM_TOTAL 115328

__global__ void cvt_w_kernel(const float* __restrict__ w, const int* __restrict__ cn) {
    int idx = blockIdx.x * blockDim.x + threadIdx.x;     // o(64) x kh(3) x kw(3) x c(32)
    if (idx >= COUT_ * 9 * CIN_) return;
    int c  = idx & 31;
    int kw = (idx >> 5) % 3;
    int kh = ((idx >> 5) / 3) % 3;
    int o  = idx / (32 * 9);
    int n  = cn[o];
    float v = 0.f;
    if (c < n)      v += w[(o * MAXCN_ + c) * 9 + kh * 3 + kw];
    if (c + 32 < n) v += w[(o * MAXCN_ + c + 32) * 9 + kh * 3 + kw];
    int k = kh * 32 + c;
    char* base = (char*)g_wfold;
    *(__half*)(base + ((size_t)kw * 64 + o) * WSTRIDE + k * 2) = __float2half_rn(v);
}

// x -> fp16 in stage-ready layout [b][row][px][c]
__global__ void cvt_x_kernel(const float* __restrict__ x) {
    __shared__ float s[CIN_][129];
    const int row = blockIdx.x, b = blockIdx.y, tid = threadIdx.x;
    for (int i = tid; i < CIN_ * W_; i += 256) {
        int c = i >> 7, px = i & 127;
        s[c][px] = x[(((size_t)b * CIN_ + c) * H_ + row) * W_ + px];   // coalesced over px
    }
    __syncthreads();
    for (int q = tid; q < 512; q += 256) {
        int px = q >> 2, c0 = (q & 3) * 8;
        __align__(16) __half v[8];
        #pragma unroll
        for (int j = 0; j < 8; ++j) v[j] = __float2half_rn(s[c0 + j][px]);
        g_xcvt[((size_t)b * H_ + row) * 512 + q] = *(const uint4*)v;
    }
}

__device__ __forceinline__ uint32_t smem_u32(const void* p) {
    uint32_t a;
    asm("{ .reg .u64 t; cvta.to.shared.u64 t, %1; cvt.u32.u64 %0, t; }" : "=r"(a) : "l"(p));
    return a;
}
__device__ __forceinline__ void ldsm4(uint32_t* r, uint32_t addr) {
    asm volatile("ldmatrix.sync.aligned.m8n8.x4.shared.b16 {%0,%1,%2,%3}, [%4];"
                 : "=r"(r[0]), "=r"(r[1]), "=r"(r[2]), "=r"(r[3]) : "r"(addr));
}
__device__ __forceinline__ void mma16816(float (&d)[4], const uint32_t* a,
                                         uint32_t b0, uint32_t b1) {
    asm volatile("mma.sync.aligned.m16n8k16.row.col.f32.f16.f16.f32 "
                 "{%0,%1,%2,%3}, {%4,%5,%6,%7}, {%8,%9}, {%0,%1,%2,%3};"
                 : "+f"(d[0]), "+f"(d[1]), "+f"(d[2]), "+f"(d[3])
                 : "r"(a[0]), "r"(a[1]), "r"(a[2]), "r"(a[3]), "r"(b0), "r"(b1));
}

__global__ __launch_bounds__(512, 1)
void conv_kernel(const float* __restrict__ bias, float* __restrict__ out) {
    extern __shared__ __align__(128) char smem[];
    const uint32_t sb = smem_u32(smem);
    const int tid  = threadIdx.x;
    const int lane = tid & 31;
    const int w    = tid >> 5;          // 16 warps
    const int g    = w & 7;             // px group (16 px)
    const int oh   = w >> 3;            // oc half  (32 oc)
    const int px0  = g * 16;
    const int b    = blockIdx.x;
    const int r0   = blockIdx.y * TILES;

    // zero X pad px-rows 128,129 of all 4 ring slots
    for (int i = tid; i < 40; i += 512) {
        int slot = i / 10, rem = i % 10, rr = rem / 5, q = rem % 5;
        uint4 z = {0, 0, 0, 0};
        *(uint4*)(smem + OFF_X + (size_t)slot * XSIZE + (128 + rr) * XSTRIDE + q * 16) = z;
    }
    // copy W (layout-identical)
    for (int i = tid; i < 2496; i += 512)
        ((uint4*)smem)[i] = g_wfold[i];

    // prologue: stage rows r0..r0+3 (1 uint4 per thread per row)
    const uint4* xg = g_xcvt + (size_t)b * H_ * 512;
    #pragma unroll
    for (int j = 0; j < 4; ++j) {
        uint4 v = xg[(size_t)(r0 + j) * 512 + tid];
        *(uint4*)(smem + OFF_X + (size_t)((r0 + j) & 3) * XSIZE
                  + (tid >> 2) * XSTRIDE + (tid & 3) * 16) = v;
    }
    __syncthreads();

    const uint32_t a_lane = (uint32_t)(((lane & 7) + ((lane >> 3) & 1) * 8) * XSTRIDE
                                       + ((lane >> 4) & 1) * 16);
    const uint32_t b_lane = (uint32_t)(((lane & 7) + ((lane >> 4) & 1) * 8) * WSTRIDE
                                       + ((lane >> 3) & 1) * 16);

    for (int pl = 0; pl < TILES / 2; ++pl) {
        const int rg = r0 + 2 * pl;

        // register prefetch next row pair (hidden behind compute)
        uint4 pf0, pf1;
        if (pl < 6) {
            pf0 = xg[(size_t)(rg + 4) * 512 + tid];
            pf1 = xg[(size_t)(rg + 5) * 512 + tid];
        }

        float acc[2][4][4];
        #pragma unroll
        for (int rr = 0; rr < 2; ++rr)
            #pragma unroll
            for (int t = 0; t < 4; ++t)
                #pragma unroll
                for (int j = 0; j < 4; ++j) acc[rr][t][j] = 0.f;

        #pragma unroll
        for (int s = 0; s < 6; ++s) {
            const int kh = s >> 1;
            const uint32_t acoff = (s & 1) * 32;
            const uint32_t bcoff = (uint32_t)(kh * 64 + (s & 1) * 32);
            #pragma unroll
            for (int kw = 0; kw < 3; ++kw) {
                uint32_t bh[8];
                const uint32_t wb = sb + OFF_W + (uint32_t)kw * WSIZE
                                  + (uint32_t)(oh * 32) * WSTRIDE + bcoff + b_lane;
                ldsm4(bh,     wb);
                ldsm4(bh + 4, wb + 16u * WSTRIDE);
                #pragma unroll
                for (int rr = 0; rr < 2; ++rr) {
                    const int slot = (rg + rr + kh) & 3;
                    const uint32_t aaddr = sb + OFF_X + (uint32_t)slot * XSIZE
                                         + (uint32_t)(px0 + kw) * XSTRIDE + acoff + a_lane;
                    uint32_t ah[4];
                    ldsm4(ah, aaddr);
                    #pragma unroll
                    for (int t = 0; t < 4; ++t)
                        mma16816(acc[rr][t], ah, bh[2 * t], bh[2 * t + 1]);
                }
            }
        }

        __syncthreads();                     // X reads + prev E readers done
        if (pl < 6) {
            *(uint4*)(smem + OFF_X + (size_t)((rg + 4) & 3) * XSIZE
                      + (tid >> 2) * XSTRIDE + (tid & 3) * 16) = pf0;
            *(uint4*)(smem + OFF_X + (size_t)((rg + 5) & 3) * XSIZE
                      + (tid >> 2) * XSTRIDE + (tid & 3) * 16) = pf1;
        }

        #pragma unroll
        for (int rr = 0; rr < 2; ++rr) {
            const int ho = rg + rr;
            if (rr == 1) __syncthreads();    // row-0 E readers done
            #pragma unroll
            for (int t = 0; t < 4; ++t)
                #pragma unroll
                for (int j = 0; j < 4; ++j) {
                    const int oc = oh * 32 + t * 8 + (lane & 3) * 2 + (j & 1);
                    const int wo = px0 + (lane >> 2) + (j >> 1) * 8;
                    *(float*)(smem + OFF_E + (size_t)(oc * 132 + wo) * 4) = acc[rr][t][j];
                }
            __syncthreads();
            #pragma unroll
            for (int i = 0; i < 4; ++i) {
                const int idx = i * 512 + tid;
                const int oc = idx >> 5, wo4 = (idx & 31) * 4;
                uint4 e = *(const uint4*)(smem + OFF_E + (size_t)(oc * 132 + wo4) * 4);
                const float ev[4] = {__uint_as_float(e.x), __uint_as_float(e.y),
                                     __uint_as_float(e.z), __uint_as_float(e.w)};
                #pragma unroll
                for (int m = 0; m < 4; ++m) {
                    const int wo = wo4 + m;
                    if (wo < WO_) {
                        float v = ev[m] + __ldg(bias + ((size_t)oc * HO_ + ho) * WO_ + wo);
                        out[(((size_t)b * COUT_ + oc) * HO_ + ho) * WO_ + wo] = v;
                    }
                }
            }
        }
    }
}

extern "C" void kernel_launch(void* const* d_in, const int* in_sizes, int n_in,
                              void* d_out, int out_size) {
    const float* x    = (const float*)d_in[0];   // [32,32,128,128]
    const float* w    = (const float*)d_in[1];   // [64,64,3,3]
    const float* bias = (const float*)d_in[2];   // [64,126,126]
    const int*   cn   = (const int*)d_in[3];     // [64]
    float* out = (float*)d_out;                  // [32,64,126,126]

    cvt_w_kernel<<<(COUT_ * 9 * CIN_ + 255) / 256, 256>>>(w, cn);
    cvt_x_kernel<<<dim3(H_, B_), 256>>>(x);
    cudaFuncSetAttribute(conv_kernel, cudaFuncAttributeMaxDynamicSharedMemorySize, SMEM_TOTAL);
    conv_kernel<<<dim3(B_, 9), 512, SMEM_TOTAL>>>(bias, out);
}

// round 14
// speedup vs baseline: 4.2402x; 1.0671x over previous
#include <cuda_runtime.h>
#include <cuda_fp16.h>
#include <cstdint>

#define B_    32
#define CIN_  32
#define COUT_ 64
#define H_    128
#define W_    128
#define HO_   126
#define WO_   126
#define MAXCN_ 64
#define TILES 14           // output rows per CTA strip; 9 strips x 14 = 126

// ---------------- prepared global buffers ----------------
// X fp16: [b][row][px 128][c 32], 512 uint4 per (b,row) -> 32 MB
__device__ uint4 g_xcvt[(size_t)B_ * H_ * 512];
// W folded fp16: [kw][oc 64][k 96 pad->104] -> 39936 B
__device__ uint4 g_wfold[2496];

// ---------------- smem layout (bytes) ----------------
#define WSTRIDE 208
#define WSIZE   13312        // 64 * 208
#define OFF_W   0
#define XSTRIDE 80           // 32c fp16 = 64B + 16B pad (odd multiple of 16): ldsm conflict-free
#define XSIZE   10400        // 130 px-rows * 80
#define OFF_X   39936        // 3 * WSIZE
#define OFF_E   81536        // OFF_X + 4*XSIZE ; E: [oc 32][wo pad 132] f32 = 16896 B
#define SMEM_TOTAL 98432     // -> 2 CTAs per SM

// fused prep: every block converts one (b,row) of X; first 72 blocks also fold W
__global__ void prep_kernel(const float* __restrict__ x,
                            const float* __restrict__ w,
                            const int* __restrict__ cn) {
    __shared__ float s[CIN_][129];
    const int row = blockIdx.x, b = blockIdx.y, tid = threadIdx.x;

    const int bid = blockIdx.y * gridDim.x + blockIdx.x;
    if (bid < 72) {
        int idx = bid * 256 + tid;            // o(64) x kh(3) x kw(3) x c(32) = 18432
        int c  = idx & 31;
        int kw = (idx >> 5) % 3;
        int kh = ((idx >> 5) / 3) % 3;
        int o  = idx / (32 * 9);
        int n  = cn[o];
        float v = 0.f;
        if (c < n)      v += w[(o * MAXCN_ + c) * 9 + kh * 3 + kw];
        if (c + 32 < n) v += w[(o * MAXCN_ + c + 32) * 9 + kh * 3 + kw];
        int k = kh * 32 + c;
        *(__half*)((char*)g_wfold + ((size_t)kw * 64 + o) * WSTRIDE + k * 2) = __float2half_rn(v);
    }

    for (int i = tid; i < CIN_ * W_; i += 256) {
        int c = i >> 7, px = i & 127;
        s[c][px] = x[(((size_t)b * CIN_ + c) * H_ + row) * W_ + px];   // coalesced over px
    }
    __syncthreads();
    for (int q = tid; q < 512; q += 256) {
        int px = q >> 2, c0 = (q & 3) * 8;
        __align__(16) __half v[8];
        #pragma unroll
        for (int j = 0; j < 8; ++j) v[j] = __float2half_rn(s[c0 + j][px]);
        g_xcvt[((size_t)b * H_ + row) * 512 + q] = *(const uint4*)v;
    }
}

__device__ __forceinline__ uint32_t smem_u32(const void* p) {
    uint32_t a;
    asm("{ .reg .u64 t; cvta.to.shared.u64 t, %1; cvt.u32.u64 %0, t; }" : "=r"(a) : "l"(p));
    return a;
}
__device__ __forceinline__ void ldsm4(uint32_t* r, uint32_t addr) {
    asm volatile("ldmatrix.sync.aligned.m8n8.x4.shared.b16 {%0,%1,%2,%3}, [%4];"
                 : "=r"(r[0]), "=r"(r[1]), "=r"(r[2]), "=r"(r[3]) : "r"(addr));
}
__device__ __forceinline__ void mma16816(float (&d)[4], const uint32_t* a,
                                         uint32_t b0, uint32_t b1) {
    asm volatile("mma.sync.aligned.m16n8k16.row.col.f32.f16.f16.f32 "
                 "{%0,%1,%2,%3}, {%4,%5,%6,%7}, {%8,%9}, {%0,%1,%2,%3};"
                 : "+f"(d[0]), "+f"(d[1]), "+f"(d[2]), "+f"(d[3])
                 : "r"(a[0]), "r"(a[1]), "r"(a[2]), "r"(a[3]), "r"(b0), "r"(b1));
}

__global__ __launch_bounds__(256, 2)
void conv_kernel(const float* __restrict__ bias, float* __restrict__ out) {
    extern __shared__ __align__(128) char smem[];
    const uint32_t sb = smem_u32(smem);
    const int tid  = threadIdx.x;
    const int lane = tid & 31;
    const int w    = tid >> 5;          // 8 warps; each: 16 px x 64 oc x 2 rows
    const int px0  = w * 16;
    const int b    = blockIdx.x;
    const int r0   = blockIdx.y * TILES;

    // zero X pad px-rows 128,129 of all 4 ring slots (4*2*5 = 40 uint4)
    for (int i = tid; i < 40; i += 256) {
        int slot = i / 10, rem = i % 10, rr = rem / 5, q = rem % 5;
        uint4 z = {0, 0, 0, 0};
        *(uint4*)(smem + OFF_X + (size_t)slot * XSIZE + (128 + rr) * XSTRIDE + q * 16) = z;
    }
    // copy W (layout-identical)
    for (int i = tid; i < 2496; i += 256)
        ((uint4*)smem)[i] = g_wfold[i];

    // prologue: stage rows r0..r0+3 (512 uint4 per row, 2 per thread)
    const uint4* xg = g_xcvt + (size_t)b * H_ * 512;
    #pragma unroll
    for (int j = 0; j < 4; ++j)
        #pragma unroll
        for (int k = 0; k < 2; ++k) {
            int q = tid + k * 256;
            uint4 v = xg[(size_t)(r0 + j) * 512 + q];
            *(uint4*)(smem + OFF_X + (size_t)((r0 + j) & 3) * XSIZE
                      + (q >> 2) * XSTRIDE + (q & 3) * 16) = v;
        }
    __syncthreads();

    const uint32_t a_lane = (uint32_t)(((lane & 7) + ((lane >> 3) & 1) * 8) * XSTRIDE
                                       + ((lane >> 4) & 1) * 16);
    const uint32_t b_lane = (uint32_t)(((lane & 7) + ((lane >> 4) & 1) * 8) * WSTRIDE
                                       + ((lane >> 3) & 1) * 16);

    for (int pl = 0; pl < TILES / 2; ++pl) {
        const int rg = r0 + 2 * pl;

        // register prefetch next row pair
        uint4 pf[4];
        if (pl < 6) {
            #pragma unroll
            for (int k = 0; k < 4; ++k) {
                int rowi = k >> 1, q = tid + (k & 1) * 256;
                pf[k] = xg[(size_t)(rg + 4 + rowi) * 512 + q];
            }
        }

        float acc[2][8][4];
        #pragma unroll
        for (int rr = 0; rr < 2; ++rr)
            #pragma unroll
            for (int t = 0; t < 8; ++t)
                #pragma unroll
                for (int j = 0; j < 4; ++j) acc[rr][t][j] = 0.f;

        #pragma unroll
        for (int s = 0; s < 6; ++s) {
            const int kh = s >> 1;
            const uint32_t acoff = (s & 1) * 32;
            const uint32_t bcoff = (uint32_t)(kh * 64 + (s & 1) * 32);
            #pragma unroll
            for (int kw = 0; kw < 3; ++kw) {
                uint32_t bh[16];
                const uint32_t wb = sb + OFF_W + (uint32_t)kw * WSIZE + bcoff + b_lane;
                ldsm4(bh,      wb);
                ldsm4(bh + 4,  wb + 16u * WSTRIDE);
                ldsm4(bh + 8,  wb + 32u * WSTRIDE);
                ldsm4(bh + 12, wb + 48u * WSTRIDE);
                #pragma unroll
                for (int rr = 0; rr < 2; ++rr) {
                    const int slot = (rg + rr + kh) & 3;
                    const uint32_t aaddr = sb + OFF_X + (uint32_t)slot * XSIZE
                                         + (uint32_t)(px0 + kw) * XSTRIDE + acoff + a_lane;
                    uint32_t ah[4];
                    ldsm4(ah, aaddr);
                    #pragma unroll
                    for (int t = 0; t < 8; ++t)
                        mma16816(acc[rr][t], ah, bh[2 * t], bh[2 * t + 1]);
                }
            }
        }

        bool stored_pf = false;
        #pragma unroll
        for (int rr = 0; rr < 2; ++rr) {
            const int ho = rg + rr;
            #pragma unroll
            for (int hh = 0; hh < 2; ++hh) {
                __syncthreads();             // prev E reads done / compute X reads done
                if (!stored_pf) {            // X slots rg,rg+1 now safe to overwrite
                    if (pl < 6) {
                        #pragma unroll
                        for (int k = 0; k < 4; ++k) {
                            int rowi = k >> 1, q = tid + (k & 1) * 256;
                            *(uint4*)(smem + OFF_X + (size_t)((rg + 4 + rowi) & 3) * XSIZE
                                      + (q >> 2) * XSTRIDE + (q & 3) * 16) = pf[k];
                        }
                    }
                    stored_pf = true;
                }
                #pragma unroll
                for (int t = 0; t < 4; ++t)
                    #pragma unroll
                    for (int j = 0; j < 4; ++j) {
                        const int eoc = t * 8 + (lane & 3) * 2 + (j & 1);   // 0..31
                        const int wo  = px0 + (lane >> 2) + (j >> 1) * 8;
                        *(float*)(smem + OFF_E + (size_t)(eoc * 132 + wo) * 4)
                            = acc[rr][hh * 4 + t][j];
                    }
                __syncthreads();
                #pragma unroll
                for (int i = 0; i < 4; ++i) {
                    const int idx = i * 256 + tid;
                    const int eoc = idx >> 5, wo4 = (idx & 31) * 4;
                    const int oc  = hh * 32 + eoc;
                    uint4 e = *(const uint4*)(smem + OFF_E + (size_t)(eoc * 132 + wo4) * 4);
                    const float ev[4] = {__uint_as_float(e.x), __uint_as_float(e.y),
                                         __uint_as_float(e.z), __uint_as_float(e.w)};
                    #pragma unroll
                    for (int m = 0; m < 4; ++m) {
                        const int wo = wo4 + m;
                        if (wo < WO_) {
                            float v = ev[m] + __ldg(bias + ((size_t)oc * HO_ + ho) * WO_ + wo);
                            out[(((size_t)b * COUT_ + oc) * HO_ + ho) * WO_ + wo] = v;
                        }
                    }
                }
            }
        }
        __syncthreads();                     // E reads done before next pair's writes
    }
}

extern "C" void kernel_launch(void* const* d_in, const int* in_sizes, int n_in,
                              void* d_out, int out_size) {
    const float* x    = (const float*)d_in[0];   // [32,32,128,128]
    const float* w    = (const float*)d_in[1];   // [64,64,3,3]
    const float* bias = (const float*)d_in[2];   // [64,126,126]
    const int*   cn   = (const int*)d_in[3];     // [64]
    float* out = (float*)d_out;                  // [32,64,126,126]

    prep_kernel<<<dim3(H_, B_), 256>>>(x, w, cn);
    cudaFuncSetAttribute(conv_kernel, cudaFuncAttributeMaxDynamicSharedMemorySize, SMEM_TOTAL);
    conv_kernel<<<dim3(B_, 9), 256, SMEM_TOTAL>>>(bias, out);
}

// round 15
// speedup vs baseline: 5.0667x; 1.1949x over previous
#include <cuda_runtime.h>
#include <cuda_fp16.h>
#include <cstdint>

#define B_    32
#define CIN_  32
#define COUT_ 64
#define H_    128
#define W_    128
#define HO_   126
#define WO_   126
#define MAXCN_ 64
#define TILES 14           // output rows per CTA strip; 9 strips x 14 = 126

// ---------------- prepared global buffers ----------------
// X fp16: [b][row][px 128][c 32], 512 uint4 per (b,row) -> 32 MB
__device__ uint4 g_xcvt[(size_t)B_ * H_ * 512];
// W folded fp16: [kw][oc 64][k 96 pad->104] -> 39936 B
__device__ uint4 g_wfold[2496];

// ---------------- smem layout (bytes) ----------------
#define WSTRIDE 208
#define WSIZE   13312        // 64 * 208
#define OFF_W   0
#define XSTRIDE 80           // 32c fp16 = 64B + 16B pad: ldsm conflict-free phases
#define XSIZE   10400        // 130 px-rows * 80
#define OFF_X   39936        // 3 * WSIZE
#define SMEM_TOTAL 81536     // OFF_X + 4*XSIZE  -> 2 CTAs/SM with headroom

// prep: each block converts TWO (b,row) X-rows; first 36 blocks also fold W
__global__ __launch_bounds__(512)
void prep_kernel(const float* __restrict__ x,
                 const float* __restrict__ w,
                 const int* __restrict__ cn) {
    __shared__ float s[2][CIN_][129];
    const int row0 = blockIdx.x * 2, b = blockIdx.y, tid = threadIdx.x;

    const int bid = blockIdx.y * gridDim.x + blockIdx.x;
    if (bid < 36) {
        int idx = bid * 512 + tid;            // o(64) x kh(3) x kw(3) x c(32) = 18432
        int c  = idx & 31;
        int kw = (idx >> 5) % 3;
        int kh = ((idx >> 5) / 3) % 3;
        int o  = idx / (32 * 9);
        int n  = cn[o];
        float v = 0.f;
        if (c < n)      v += w[(o * MAXCN_ + c) * 9 + kh * 3 + kw];
        if (c + 32 < n) v += w[(o * MAXCN_ + c + 32) * 9 + kh * 3 + kw];
        int k = kh * 32 + c;
        *(__half*)((char*)g_wfold + ((size_t)kw * 64 + o) * WSTRIDE + k * 2) = __float2half_rn(v);
    }

    for (int i = tid; i < 2 * CIN_ * W_; i += 512) {
        int r = i >> 12, rem = i & 4095, c = rem >> 7, px = rem & 127;
        s[r][c][px] = x[(((size_t)b * CIN_ + c) * H_ + row0 + r) * W_ + px];  // coalesced over px
    }
    __syncthreads();
    for (int q2 = tid; q2 < 1024; q2 += 512) {
        int r = q2 >> 9, q = q2 & 511;
        int px = q >> 2, c0 = (q & 3) * 8;
        __align__(16) __half v[8];
        #pragma unroll
        for (int j = 0; j < 8; ++j) v[j] = __float2half_rn(s[r][c0 + j][px]);
        g_xcvt[((size_t)b * H_ + row0 + r) * 512 + q] = *(const uint4*)v;
    }
}

__device__ __forceinline__ uint32_t smem_u32(const void* p) {
    uint32_t a;
    asm("{ .reg .u64 t; cvta.to.shared.u64 t, %1; cvt.u32.u64 %0, t; }" : "=r"(a) : "l"(p));
    return a;
}
__device__ __forceinline__ void ldsm4(uint32_t* r, uint32_t addr) {
    asm volatile("ldmatrix.sync.aligned.m8n8.x4.shared.b16 {%0,%1,%2,%3}, [%4];"
                 : "=r"(r[0]), "=r"(r[1]), "=r"(r[2]), "=r"(r[3]) : "r"(addr));
}
__device__ __forceinline__ void mma16816(float (&d)[4], const uint32_t* a,
                                         uint32_t b0, uint32_t b1) {
    asm volatile("mma.sync.aligned.m16n8k16.row.col.f32.f16.f16.f32 "
                 "{%0,%1,%2,%3}, {%4,%5,%6,%7}, {%8,%9}, {%0,%1,%2,%3};"
                 : "+f"(d[0]), "+f"(d[1]), "+f"(d[2]), "+f"(d[3])
                 : "r"(a[0]), "r"(a[1]), "r"(a[2]), "r"(a[3]), "r"(b0), "r"(b1));
}

__global__ __launch_bounds__(256, 2)
void conv_kernel(const float* __restrict__ bias, float* __restrict__ out) {
    extern __shared__ __align__(128) char smem[];
    const uint32_t sb = smem_u32(smem);
    const int tid  = threadIdx.x;
    const int lane = tid & 31;
    const int w    = tid >> 5;          // 8 warps; each: 16 px x 64 oc x 2 rows
    const int px0  = w * 16;
    const int b    = blockIdx.x;
    const int r0   = blockIdx.y * TILES;

    // zero X pad px-rows 128,129 of all 4 ring slots
    for (int i = tid; i < 40; i += 256) {
        int slot = i / 10, rem = i % 10, rr = rem / 5, q = rem % 5;
        uint4 z = {0, 0, 0, 0};
        *(uint4*)(smem + OFF_X + (size_t)slot * XSIZE + (128 + rr) * XSTRIDE + q * 16) = z;
    }
    // copy W (layout-identical)
    for (int i = tid; i < 2496; i += 256)
        ((uint4*)smem)[i] = g_wfold[i];

    // prologue: stage rows r0..r0+3
    const uint4* xg = g_xcvt + (size_t)b * H_ * 512;
    #pragma unroll
    for (int j = 0; j < 4; ++j)
        #pragma unroll
        for (int k = 0; k < 2; ++k) {
            int q = tid + k * 256;
            uint4 v = xg[(size_t)(r0 + j) * 512 + q];
            *(uint4*)(smem + OFF_X + (size_t)((r0 + j) & 3) * XSIZE
                      + (q >> 2) * XSTRIDE + (q & 3) * 16) = v;
        }
    __syncthreads();

    const uint32_t a_lane = (uint32_t)(((lane & 7) + ((lane >> 3) & 1) * 8) * XSTRIDE
                                       + ((lane >> 4) & 1) * 16);
    const uint32_t b_lane = (uint32_t)(((lane & 7) + ((lane >> 4) & 1) * 8) * WSTRIDE
                                       + ((lane >> 3) & 1) * 16);

    // per-thread epilogue coordinates
    const int wo_base = px0 + (lane >> 2);       // + (j>>1)*8
    const int oc_base = (lane & 3) * 2;          // + t*8 + (j&1)

    for (int pl = 0; pl < TILES / 2; ++pl) {
        const int rg = r0 + 2 * pl;

        // register prefetch next row pair
        uint4 pf[4];
        if (pl < 6) {
            #pragma unroll
            for (int k = 0; k < 4; ++k) {
                int rowi = k >> 1, q = tid + (k & 1) * 256;
                pf[k] = xg[(size_t)(rg + 4 + rowi) * 512 + q];
            }
        }

        float acc[2][8][4];
        #pragma unroll
        for (int rr = 0; rr < 2; ++rr)
            #pragma unroll
            for (int t = 0; t < 8; ++t)
                #pragma unroll
                for (int j = 0; j < 4; ++j) acc[rr][t][j] = 0.f;

        #pragma unroll
        for (int s = 0; s < 6; ++s) {
            const int kh = s >> 1;
            const uint32_t acoff = (s & 1) * 32;
            const uint32_t bcoff = (uint32_t)(kh * 64 + (s & 1) * 32);
            #pragma unroll
            for (int kw = 0; kw < 3; ++kw) {
                uint32_t bh[16];
                const uint32_t wb = sb + OFF_W + (uint32_t)kw * WSIZE + bcoff + b_lane;
                ldsm4(bh,      wb);
                ldsm4(bh + 4,  wb + 16u * WSTRIDE);
                ldsm4(bh + 8,  wb + 32u * WSTRIDE);
                ldsm4(bh + 12, wb + 48u * WSTRIDE);
                #pragma unroll
                for (int rr = 0; rr < 2; ++rr) {
                    const int slot = (rg + rr + kh) & 3;
                    const uint32_t aaddr = sb + OFF_X + (uint32_t)slot * XSIZE
                                         + (uint32_t)(px0 + kw) * XSTRIDE + acoff + a_lane;
                    uint32_t ah[4];
                    ldsm4(ah, aaddr);
                    #pragma unroll
                    for (int t = 0; t < 8; ++t)
                        mma16816(acc[rr][t], ah, bh[2 * t], bh[2 * t + 1]);
                }
            }
        }

        __syncthreads();                     // all X reads done -> slots reusable
        if (pl < 6) {                        // stage next pair (latency overlapped by epilogue)
            #pragma unroll
            for (int k = 0; k < 4; ++k) {
                int rowi = k >> 1, q = tid + (k & 1) * 256;
                *(uint4*)(smem + OFF_X + (size_t)((rg + 4 + rowi) & 3) * XSIZE
                          + (q >> 2) * XSTRIDE + (q & 3) * 16) = pf[k];
            }
        }

        // direct-STG epilogue: per (t,j) a 4oc x 8wo block per warp; full 32B sectors
        #pragma unroll
        for (int rr = 0; rr < 2; ++rr) {
            const int ho = rg + rr;
            #pragma unroll
            for (int t = 0; t < 8; ++t) {
                const int oc = t * 8 + oc_base;
                const float* pb = bias + ((size_t)oc * HO_ + ho) * WO_ + wo_base;
                float* po = out + (((size_t)b * COUT_ + oc) * HO_ + ho) * WO_ + wo_base;
                #pragma unroll
                for (int j = 0; j < 4; ++j) {
                    const int wo = wo_base + (j >> 1) * 8;
                    if (wo < WO_) {
                        const size_t off = (size_t)(j & 1) * (HO_ * WO_) + (j >> 1) * 8;
                        po[off] = acc[rr][t][j] + __ldg(pb + off);
                    }
                }
            }
        }
        __syncthreads();                     // staged X visible before next compute
    }
}

extern "C" void kernel_launch(void* const* d_in, const int* in_sizes, int n_in,
                              void* d_out, int out_size) {
    const float* x    = (const float*)d_in[0];   // [32,32,128,128]
    const float* w    = (const float*)d_in[1];   // [64,64,3,3]
    const float* bias = (const float*)d_in[2];   // [64,126,126]
    const int*   cn   = (const int*)d_in[3];     // [64]
    float* out = (float*)d_out;                  // [32,64,126,126]

    prep_kernel<<<dim3(H_ / 2, B_), 512>>>(x, w, cn);
    cudaFuncSetAttribute(conv_kernel, cudaFuncAttributeMaxDynamicSharedMemorySize, SMEM_TOTAL);
    conv_kernel<<<dim3(B_, 9), 256, SMEM_TOTAL>>>(bias, out);
}

// round 16
// speedup vs baseline: 6.0458x; 1.1932x over previous
#include <cuda_runtime.h>
#include <cuda_fp16.h>
#include <cstdint>

#define B_    32
#define CIN_  32
#define COUT_ 64
#define H_    128
#define W_    128
#define HO_   126
#define WO_   126
#define MAXCN_ 64
#define TILES 14           // output rows per CTA strip; 9 strips x 14 = 126

// ---------------- smem layout (bytes) ----------------
#define WSTRIDE 208
#define WSIZE   13312        // 64 * 208
#define OFF_W   0
#define XSTRIDE 80           // 32c fp16 = 64B + 16B pad
#define XSIZE   10400        // 130 px-rows * 80
#define OFF_X   39936        // 3 * WSIZE
#define SMEM_TOTAL 81536     // OFF_X + 4*XSIZE  -> 2 CTAs/SM

__device__ __forceinline__ uint32_t smem_u32(const void* p) {
    uint32_t a;
    asm("{ .reg .u64 t; cvta.to.shared.u64 t, %1; cvt.u32.u64 %0, t; }" : "=r"(a) : "l"(p));
    return a;
}
__device__ __forceinline__ void ldsm4(uint32_t* r, uint32_t addr) {
    asm volatile("ldmatrix.sync.aligned.m8n8.x4.shared.b16 {%0,%1,%2,%3}, [%4];"
                 : "=r"(r[0]), "=r"(r[1]), "=r"(r[2]), "=r"(r[3]) : "r"(addr));
}
__device__ __forceinline__ void mma16816(float (&d)[4], const uint32_t* a,
                                         uint32_t b0, uint32_t b1) {
    asm volatile("mma.sync.aligned.m16n8k16.row.col.f32.f16.f16.f32 "
                 "{%0,%1,%2,%3}, {%4,%5,%6,%7}, {%8,%9}, {%0,%1,%2,%3};"
                 : "+f"(d[0]), "+f"(d[1]), "+f"(d[2]), "+f"(d[3])
                 : "r"(a[0]), "r"(a[1]), "r"(a[2]), "r"(a[3]), "r"(b0), "r"(b1));
}

// LDG two rows (ra, ra+1): 32 floats per thread, coalesced over px
__device__ __forceinline__ void ldg_pair(const float* __restrict__ xb, int ra, int tid,
                                         float* f) {
    #pragma unroll
    for (int it = 0; it < 16; ++it) {
        const int i  = it * 256 + tid;
        const int r  = i >> 11;            // 0..1
        const int cp = (i >> 7) & 15;      // channel pair
        const int px = i & 127;            // lane-consecutive -> coalesced
        f[2 * it]     = __ldg(xb + ((size_t)(2 * cp)     * H_ + ra + r) * W_ + px);
        f[2 * it + 1] = __ldg(xb + ((size_t)(2 * cp + 1) * H_ + ra + r) * W_ + px);
    }
}
// convert + store into ring slots (ra&3), (ra+1)&3, layout [px][c]
__device__ __forceinline__ void sts_pair(char* smem, int ra, int tid, const float* f) {
    #pragma unroll
    for (int it = 0; it < 16; ++it) {
        const int i  = it * 256 + tid;
        const int r  = i >> 11;
        const int cp = (i >> 7) & 15;
        const int px = i & 127;
        __half2 h = __floats2half2_rn(f[2 * it], f[2 * it + 1]);
        *(__half2*)(smem + OFF_X + (size_t)((ra + r) & 3) * XSIZE
                    + px * XSTRIDE + cp * 4) = h;
    }
}

__global__ __launch_bounds__(256, 2)
void conv_kernel(const float* __restrict__ x, const float* __restrict__ w,
                 const float* __restrict__ bias, const int* __restrict__ cn,
                 float* __restrict__ out) {
    extern __shared__ __align__(128) char smem[];
    const uint32_t sb = smem_u32(smem);
    const int tid  = threadIdx.x;
    const int lane = tid & 31;
    const int wp   = tid >> 5;          // 8 warps; each: 16 px x 64 oc x 2 rows
    const int px0  = wp * 16;
    const int b    = blockIdx.x;
    const int r0   = blockIdx.y * TILES;
    const float* xb = x + (size_t)b * CIN_ * H_ * W_;

    // zero X pad px-rows 128,129 of all 4 ring slots
    for (int i = tid; i < 40; i += 256) {
        int slot = i / 10, rem = i % 10, rr = rem / 5, q = rem % 5;
        uint4 z = {0, 0, 0, 0};
        *(uint4*)(smem + OFF_X + (size_t)slot * XSIZE + (128 + rr) * XSTRIDE + q * 16) = z;
    }

    // fold W into smem: [kw][oc][k=kh*32+c] fp16 (one-time, from L2)
    #pragma unroll 4
    for (int it = 0; it < 72; ++it) {
        const int idx = it * 256 + tid;     // o(64) x kh(3) x kw(3) x c(32)
        const int c  = idx & 31;
        const int kw = (idx >> 5) % 3;
        const int kh = ((idx >> 5) / 3) % 3;
        const int o  = idx / (32 * 9);
        const int n  = __ldg(cn + o);
        float v = 0.f;
        if (c < n)      v += __ldg(w + ((size_t)o * MAXCN_ + c) * 9 + kh * 3 + kw);
        if (c + 32 < n) v += __ldg(w + ((size_t)o * MAXCN_ + c + 32) * 9 + kh * 3 + kw);
        *(__half*)(smem + OFF_W + ((size_t)kw * 64 + o) * WSTRIDE + (kh * 32 + c) * 2)
            = __float2half_rn(v);
    }

    // prologue: stage rows r0..r0+3
    {
        float f[32];
        ldg_pair(xb, r0, tid, f);
        sts_pair(smem, r0, tid, f);
        ldg_pair(xb, r0 + 2, tid, f);
        sts_pair(smem, r0 + 2, tid, f);
    }
    __syncthreads();

    const uint32_t a_lane = (uint32_t)(((lane & 7) + ((lane >> 3) & 1) * 8) * XSTRIDE
                                       + ((lane >> 4) & 1) * 16);
    const uint32_t b_lane = (uint32_t)(((lane & 7) + ((lane >> 4) & 1) * 8) * WSTRIDE
                                       + ((lane >> 3) & 1) * 16);
    const int wo_base = px0 + (lane >> 2);
    const int oc_base = (lane & 3) * 2;

    for (int pl = 0; pl < TILES / 2; ++pl) {
        const int rg = r0 + 2 * pl;

        float acc[2][8][4];
        #pragma unroll
        for (int rr = 0; rr < 2; ++rr)
            #pragma unroll
            for (int t = 0; t < 8; ++t)
                #pragma unroll
                for (int j = 0; j < 4; ++j) acc[rr][t][j] = 0.f;

        #pragma unroll
        for (int s = 0; s < 6; ++s) {
            const int kh = s >> 1;
            const uint32_t acoff = (s & 1) * 32;
            const uint32_t bcoff = (uint32_t)(kh * 64 + (s & 1) * 32);
            #pragma unroll
            for (int kw = 0; kw < 3; ++kw) {
                uint32_t bh[16];
                const uint32_t wb = sb + OFF_W + (uint32_t)kw * WSIZE + bcoff + b_lane;
                ldsm4(bh,      wb);
                ldsm4(bh + 4,  wb + 16u * WSTRIDE);
                ldsm4(bh + 8,  wb + 32u * WSTRIDE);
                ldsm4(bh + 12, wb + 48u * WSTRIDE);
                #pragma unroll
                for (int rr = 0; rr < 2; ++rr) {
                    const int slot = (rg + rr + kh) & 3;
                    const uint32_t aaddr = sb + OFF_X + (uint32_t)slot * XSIZE
                                         + (uint32_t)(px0 + kw) * XSTRIDE + acoff + a_lane;
                    uint32_t ah[4];
                    ldsm4(ah, aaddr);
                    #pragma unroll
                    for (int t = 0; t < 8; ++t)
                        mma16816(acc[rr][t], ah, bh[2 * t], bh[2 * t + 1]);
                }
            }
        }

        // epilogue row 0 (before sync; frees acc[0])
        {
            const int ho = rg;
            #pragma unroll
            for (int t = 0; t < 8; ++t) {
                const int oc = t * 8 + oc_base;
                const float* pb = bias + ((size_t)oc * HO_ + ho) * WO_ + wo_base;
                float* po = out + (((size_t)b * COUT_ + oc) * HO_ + ho) * WO_ + wo_base;
                #pragma unroll
                for (int j = 0; j < 4; ++j) {
                    const int wo = wo_base + (j >> 1) * 8;
                    if (wo < WO_) {
                        const size_t off = (size_t)(j & 1) * (HO_ * WO_) + (j >> 1) * 8;
                        po[off] = acc[0][t][j] + __ldg(pb + off);
                    }
                }
            }
        }

        __syncthreads();                 // all X reads done -> slots reusable

        float f[32];
        if (pl < 6) ldg_pair(xb, rg + 4, tid, f);   // LDGs in flight...

        // epilogue row 1 (...hides LDG latency)
        {
            const int ho = rg + 1;
            #pragma unroll
            for (int t = 0; t < 8; ++t) {
                const int oc = t * 8 + oc_base;
                const float* pb = bias + ((size_t)oc * HO_ + ho) * WO_ + wo_base;
                float* po = out + (((size_t)b * COUT_ + oc) * HO_ + ho) * WO_ + wo_base;
                #pragma unroll
                for (int j = 0; j < 4; ++j) {
                    const int wo = wo_base + (j >> 1) * 8;
                    if (wo < WO_) {
                        const size_t off = (size_t)(j & 1) * (HO_ * WO_) + (j >> 1) * 8;
                        po[off] = acc[1][t][j] + __ldg(pb + off);
                    }
                }
            }
        }

        if (pl < 6) sts_pair(smem, rg + 4, tid, f);
        __syncthreads();                 // staged X visible before next compute
    }
}

extern "C" void kernel_launch(void* const* d_in, const int* in_sizes, int n_in,
                              void* d_out, int out_size) {
    const float* x    = (const float*)d_in[0];   // [32,32,128,128]
    const float* w    = (const float*)d_in[1];   // [64,64,3,3]
    const float* bias = (const float*)d_in[2];   // [64,126,126]
    const int*   cn   = (const int*)d_in[3];     // [64]
    float* out = (float*)d_out;                  // [32,64,126,126]

    cudaFuncSetAttribute(conv_kernel, cudaFuncAttributeMaxDynamicSharedMemorySize, SMEM_TOTAL);
    conv_kernel<<<dim3(B_, 9), 256, SMEM_TOTAL>>>(x, w, bias, cn, out);
}